// round 15
// baseline (speedup 1.0000x reference)
#include <cuda_runtime.h>
#include <cstdint>

// TopK keep: zero all but the K=512 largest entries per 4096-wide row.
// One CTA (256 thr) per row. Row staged in SMEM via cp.async (global->smem,
// no register round-trip): no 16-float register cache -> regs ~30 ->
// __launch_bounds__(256,8) = 8 CTAs/SM to fill latency stalls. All phases
// re-read the row from smem (LDS is cheap: 3 passes x 16KB).
//
// Select (R9 structure): 1024 bins of (u>>14)-0xFD80 tile [0.875, 3.496)
// on raw float bits (candidates positive: bit order == float order).
// Parallel suffix scan -> winning bin + rank; bounded atomic append
// compacts bin (m ~ 1-4); warp-0 bitonic -> exact K-th key T.
// Exactness guards: tot<K / clamp-bin / m>CMAX -> 32-step binary-search
// fallback (smem re-reads); m>32 -> smem-loop search; need!=n_eq ->
// stable lowest-index tie ranking. Exact for any input.

#define D_DIM   4096
#define K_KEEP  512
#define NT      256
#define NW      8
#define T0F     0.875f
#define BOFF    0xFD80u      // f2u(0.875) >> 14
#define NBIN    1024
#define CMAX    512

__device__ __forceinline__ unsigned f2k(float f) {
    unsigned u = __float_as_uint(f);
    return u ^ ((unsigned)((int)u >> 31) | 0x80000000u);
}
__device__ __forceinline__ float k2f(unsigned k) {
    return __uint_as_float(k ^ ((unsigned)((int)(~k) >> 31) | 0x80000000u));
}

__global__ __launch_bounds__(NT, 8)
void topk_keep_kernel(const float* __restrict__ x, float* __restrict__ out)
{
    __shared__ __align__(16) float    fbuf[D_DIM];   // 16KB row staging
    __shared__ __align__(16) unsigned hist[NBIN];    // 4KB
    __shared__ __align__(16) unsigned cbuf[CMAX];    // 2KB
    __shared__ unsigned wsum[NW];
    __shared__ unsigned cnt, selb, selk, stot, sT, sneed, sneq;

    const int tid  = threadIdx.x;
    const int lane = tid & 31;
    const int warp = tid >> 5;
    const size_t row = (size_t)blockIdx.x * D_DIM;
    const unsigned sbase = (unsigned)__cvta_generic_to_shared(fbuf);

    // ---- cp.async: row -> smem (4 x 16B per thread), overlap hist zeroing ----
    {
        const char* g = (const char*)(x + row);
#pragma unroll
        for (int r = 0; r < 4; ++r) {
            unsigned off = (unsigned)(r * 4096 + tid * 16);
            asm volatile("cp.async.cg.shared.global [%0], [%1], 16;"
                         :: "r"(sbase + off), "l"(g + off));
        }
        asm volatile("cp.async.commit_group;" ::: "memory");
    }
    reinterpret_cast<uint4*>(hist)[tid] = make_uint4(0u,0u,0u,0u);
    if (tid == 0) cnt = 0u;
    asm volatile("cp.async.wait_group 0;" ::: "memory");
    __syncthreads();                                           // S1

    const float4* sb = reinterpret_cast<const float4*>(fbuf) + tid * 4;

    // ---- pass 1: histogram, candidates only (smem reads) ----
#pragma unroll
    for (int j = 0; j < 4; ++j) {
        float4 v = sb[j];
        if (v.x >= T0F) atomicAdd(&hist[umin((__float_as_uint(v.x) >> 14) - BOFF, 1023u)], 1u);
        if (v.y >= T0F) atomicAdd(&hist[umin((__float_as_uint(v.y) >> 14) - BOFF, 1023u)], 1u);
        if (v.z >= T0F) atomicAdd(&hist[umin((__float_as_uint(v.z) >> 14) - BOFF, 1023u)], 1u);
        if (v.w >= T0F) atomicAdd(&hist[umin((__float_as_uint(v.w) >> 14) - BOFF, 1023u)], 1u);
    }
    __syncthreads();                                           // S2

    // ---- parallel suffix scan over 1024 bins (4 bins/thread) ----
    unsigned kth = K_KEEP;
    unsigned tot;
    {
        uint4 a = reinterpret_cast<const uint4*>(hist)[tid];
        unsigned ct = a.x + a.y + a.z + a.w;
        unsigned s = ct;
#pragma unroll
        for (int o = 1; o < 32; o <<= 1) {
            unsigned v = __shfl_down_sync(0xffffffffu, s, o);
            if (lane + o < 32) s += v;
        }
        if (lane == 0) wsum[warp] = s;
        __syncthreads();                                       // S3
        unsigned addh = 0; tot = 0;
#pragma unroll
        for (int w = 0; w < NW; ++w) {
            unsigned v = wsum[w];
            tot += v;
            if (w > warp) addh += v;
        }
        if (tot >= K_KEEP) {
            unsigned beyond = (s - ct) + addh;   // count in bins above my 4
            if (beyond < kth && beyond + ct >= kth) {
                unsigned rb = beyond;
                if (rb < kth && rb + a.w >= kth) { selb = (unsigned)(tid*4+3); selk = kth - rb; }
                rb += a.w;
                if (rb < kth && rb + a.z >= kth) { selb = (unsigned)(tid*4+2); selk = kth - rb; }
                rb += a.z;
                if (rb < kth && rb + a.y >= kth) { selb = (unsigned)(tid*4+1); selk = kth - rb; }
                rb += a.y;
                if (rb < kth && rb + a.x >= kth) { selb = (unsigned)(tid*4);   selk = kth - rb; }
            }
        }
        __syncthreads();                                       // S4
    }

    bool fb = (tot < K_KEEP) || (selb == 1023u);
    unsigned binKey = 0, kk = 0, m = 0;
    if (!fb) {
        binKey = BOFF + selb;
        kk     = selk;
        // ---- pass 2: compact winning-bin values (bounded append; m ~ 1-4) ----
#pragma unroll
        for (int j = 0; j < 4; ++j) {
            float4 v = sb[j];
            unsigned uu[4] = {__float_as_uint(v.x), __float_as_uint(v.y),
                              __float_as_uint(v.z), __float_as_uint(v.w)};
#pragma unroll
            for (int c = 0; c < 4; ++c) {
                if ((uu[c] >> 14) == binKey) {
                    unsigned idx = atomicAdd(&cnt, 1u);
                    if (idx < CMAX) cbuf[idx] = uu[c];
                }
            }
        }
        __syncthreads();                                       // S5
        m = cnt;
        fb = (m > CMAX);
    }

    if (fb) {
        // ==== exact fallback: 32-step binary search (smem re-reads; ~never) ====
        unsigned lo = 0u, hi = 0xFFFFFFFFu;
#pragma unroll 1
        while (lo < hi) {
            unsigned mid = lo + ((hi - lo) >> 1) + ((hi - lo) & 1u);
            unsigned c = 0;
#pragma unroll 1
            for (int j = 0; j < 4; ++j) {
                float4 v = sb[j];
                c += (f2k(v.x) >= mid) ? 1u : 0u;
                c += (f2k(v.y) >= mid) ? 1u : 0u;
                c += (f2k(v.z) >= mid) ? 1u : 0u;
                c += (f2k(v.w) >= mid) ? 1u : 0u;
            }
            c = __reduce_add_sync(0xffffffffu, c);
            if (lane == 0) wsum[warp] = c;
            __syncthreads();
            if (warp == 0) {
                unsigned v = (lane < NW) ? wsum[lane] : 0u;
#pragma unroll
                for (int o = 4; o > 0; o >>= 1) v += __shfl_down_sync(0xffffffffu, v, o);
                if (lane == 0) stot = v;
            }
            __syncthreads();
            if (stot >= K_KEEP) lo = mid; else hi = mid - 1u;
        }
        const unsigned T = lo;
        unsigned cg = 0, ceq = 0;
#pragma unroll 1
        for (int j = 0; j < 4; ++j) {
            float4 v = sb[j];
            unsigned k4[4] = {f2k(v.x), f2k(v.y), f2k(v.z), f2k(v.w)};
#pragma unroll
            for (int c = 0; c < 4; ++c) {
                cg  += (k4[c] > T)  ? 1u : 0u;
                ceq += (k4[c] == T) ? 1u : 0u;
            }
        }
        {
            unsigned c = __reduce_add_sync(0xffffffffu, cg);
            if (lane == 0) wsum[warp] = c;
            __syncthreads();
            if (warp == 0) {
                unsigned v = (lane < NW) ? wsum[lane] : 0u;
#pragma unroll
                for (int o = 4; o > 0; o >>= 1) v += __shfl_down_sync(0xffffffffu, v, o);
                if (lane == 0) stot = v;
            }
            __syncthreads();
        }
        const unsigned need = K_KEEP - stot;
        __syncthreads();
        unsigned p = ceq;
#pragma unroll
        for (int o = 1; o < 32; o <<= 1) {
            unsigned v = __shfl_up_sync(0xffffffffu, p, o);
            if (lane >= o) p += v;
        }
        if (lane == 31) wsum[warp] = p;
        __syncthreads();
        unsigned woff = 0;
#pragma unroll
        for (int w = 0; w < NW; ++w) if (w < warp) woff += wsum[w];
        unsigned rank = woff + p - ceq;
        float4* outr = reinterpret_cast<float4*>(out + row) + tid * 4;
#pragma unroll 1
        for (int j = 0; j < 4; ++j) {
            float4 v = sb[j];
            unsigned k4[4] = {f2k(v.x), f2k(v.y), f2k(v.z), f2k(v.w)};
            float r[4];
#pragma unroll
            for (int c = 0; c < 4; ++c) {
                bool eq = (k4[c] == T);
                bool keep = (k4[c] > T) || (eq && (rank < need));
                r[c] = keep ? k2f(k4[c]) : 0.0f;
                rank += eq ? 1u : 0u;
            }
            outr[j] = make_float4(r[0], r[1], r[2], r[3]);
        }
        return;
    }

    // ---- warp-0 exact select within bin ----
    if (warp == 0) {
        if (m <= 32u) {
            // bitonic sort ascending; sentinels (0) sink to low lanes
            unsigned orig = (lane < (int)m) ? cbuf[lane] : 0u;
            unsigned v = orig;
#pragma unroll
            for (int k = 2; k <= 32; k <<= 1) {
#pragma unroll
                for (int j = k >> 1; j > 0; j >>= 1) {
                    unsigned o = __shfl_xor_sync(0xffffffffu, v, j);
                    bool dirUp   = ((lane & k) == 0);
                    bool takeMax = ((lane & j) != 0);
                    unsigned mn = umin(v, o), mx = umax(v, o);
                    v = (dirUp == takeMax) ? mx : mn;
                }
            }
            unsigned T = __shfl_sync(0xffffffffu, v, 32 - (int)kk);
            unsigned cg = __reduce_add_sync(0xffffffffu, (orig > T)  ? 1u : 0u);
            unsigned ce = __reduce_add_sync(0xffffffffu, (orig == T) ? 1u : 0u);
            if (lane == 0) { sT = T; sneed = kk - cg; sneq = ce; }
        } else {
            // rare: 14-bit binary search looping over cbuf in smem
            unsigned lo = binKey << 14, hi = (binKey << 14) | 0x3FFFu;
#pragma unroll 1
            while (lo < hi) {
                unsigned mid = lo + ((hi - lo) >> 1) + ((hi - lo) & 1u);
                unsigned c = 0;
                for (unsigned j = lane; j < m; j += 32u) c += (cbuf[j] >= mid) ? 1u : 0u;
                c = __reduce_add_sync(0xffffffffu, c);
                if (c >= kk) lo = mid; else hi = mid - 1u;
            }
            unsigned cg = 0, ce = 0;
            for (unsigned j = lane; j < m; j += 32u) {
                unsigned v = cbuf[j];
                cg += (v > lo)  ? 1u : 0u;
                ce += (v == lo) ? 1u : 0u;
            }
            cg = __reduce_add_sync(0xffffffffu, cg);
            ce = __reduce_add_sync(0xffffffffu, ce);
            if (lane == 0) { sT = lo; sneed = kk - cg; sneq = ce; }
        }
    }
    __syncthreads();                                           // S6

    const unsigned need = sneed;
    const unsigned neq  = sneq;
    const float    Tf   = __uint_as_float(sT);   // positive float

    float4* outr = reinterpret_cast<float4*>(out + row) + tid * 4;
    if (need == neq) {
        // ---- pass 3 (fast): re-read smem, emit thresholded ----
#pragma unroll
        for (int j = 0; j < 4; ++j) {
            float4 v = sb[j];
            float4 o;
            o.x = (v.x >= Tf) ? v.x : 0.0f;
            o.y = (v.y >= Tf) ? v.y : 0.0f;
            o.z = (v.z >= Tf) ? v.z : 0.0f;
            o.w = (v.w >= Tf) ? v.w : 0.0f;
            outr[j] = o;
        }
        return;
    }

    // ---- rare tie path: stable rank, lowest index first ----
    unsigned ceq = 0;
#pragma unroll 1
    for (int j = 0; j < 4; ++j) {
        float4 v = sb[j];
        ceq += (v.x == Tf) ? 1u : 0u;
        ceq += (v.y == Tf) ? 1u : 0u;
        ceq += (v.z == Tf) ? 1u : 0u;
        ceq += (v.w == Tf) ? 1u : 0u;
    }
    unsigned p = ceq;
#pragma unroll
    for (int o = 1; o < 32; o <<= 1) {
        unsigned v = __shfl_up_sync(0xffffffffu, p, o);
        if (lane >= o) p += v;
    }
    if (lane == 31) wsum[warp] = p;
    __syncthreads();
    unsigned woff = 0;
#pragma unroll
    for (int w = 0; w < NW; ++w) if (w < warp) woff += wsum[w];
    unsigned rank = woff + p - ceq;

#pragma unroll 1
    for (int j = 0; j < 4; ++j) {
        float4 v = sb[j];
        float ff[4] = {v.x, v.y, v.z, v.w};
        float r[4];
#pragma unroll
        for (int c = 0; c < 4; ++c) {
            float f = ff[c];
            bool eq = (f == Tf);
            bool keep = (f > Tf) || (eq && (rank < need));
            r[c] = keep ? f : 0.0f;
            rank += eq ? 1u : 0u;
        }
        outr[j] = make_float4(r[0], r[1], r[2], r[3]);
    }
}

extern "C" void kernel_launch(void* const* d_in, const int* in_sizes, int n_in,
                              void* d_out, int out_size) {
    const float* x = (const float*)d_in[0];
    float* out = (float*)d_out;
    int rows = out_size / D_DIM;   // 16384
    topk_keep_kernel<<<rows, NT>>>(x, out);
}

// round 16
// speedup vs baseline: 1.1476x; 1.1476x over previous
#include <cuda_runtime.h>
#include <cstdint>

// TopK keep: zero all but the K=512 largest entries per 4096-wide row.
// DEPTH-2 ROW PIPELINE: one CTA (256 thr) handles 2 rows. Row A loads to
// registers (LDG); row B streams to smem via cp.async DURING row A's
// select+emit, hiding B's DRAM latency entirely and desynchronizing the
// memory phases across the wave. Select per row = R9 structure (best known):
// 1024 bins of (u>>14)-0xFD80 tile [0.875, 3.496) on raw float bits
// (candidates positive: bit order == float order); parallel suffix scan ->
// winning bin + rank; bounded append; warp-0 bitonic -> exact K-th key.
// Guards: tot<K / clamp-bin / m>CMAX -> exact binary-search fallback;
// m>32 -> smem-loop search; need!=n_eq -> stable lowest-index ties.

#define D_DIM   4096
#define K_KEEP  512
#define NT      256
#define PT      16
#define NW      8
#define T0F     0.875f
#define BOFF    0xFD80u      // f2u(0.875) >> 14
#define NBIN    1024
#define CMAX    512

__device__ __forceinline__ unsigned f2k(float f) {
    unsigned u = __float_as_uint(f);
    return u ^ ((unsigned)((int)u >> 31) | 0x80000000u);
}
__device__ __forceinline__ float k2f(unsigned k) {
    return __uint_as_float(k ^ ((unsigned)((int)(~k) >> 31) | 0x80000000u));
}

struct Sh {
    unsigned hist[NBIN];   // 4KB
    unsigned cbuf[CMAX];   // 2KB
    unsigned wsum[NW];
    unsigned cnt, selb, selk, stot, sT, sneed, sneq;
};

__device__ __forceinline__ void zero_state(Sh* sh, int tid) {
    reinterpret_cast<uint4*>(sh->hist)[tid] = make_uint4(0u,0u,0u,0u);
    if (tid == 0) sh->cnt = 0u;
}

// Full exact select + emit for one row whose 16 values live in f0.
// Preconditions: sh->hist zeroed, sh->cnt==0, block synced.
// All branches are block-uniform. May use sh->* until it returns.
__device__ __forceinline__ void process_row(float (&f0)[PT], float* __restrict__ outrow,
                                            Sh* sh, int tid, int lane, int warp)
{
    // ---- histogram, candidates only ----
#pragma unroll
    for (int i = 0; i < PT; ++i) {
        if (f0[i] >= T0F)
            atomicAdd(&sh->hist[umin((__float_as_uint(f0[i]) >> 14) - BOFF, 1023u)], 1u);
    }
    __syncthreads();

    // ---- parallel suffix scan over 1024 bins (4/thread) ----
    unsigned kth = K_KEEP;
    unsigned tot;
    {
        uint4 a = reinterpret_cast<const uint4*>(sh->hist)[tid];
        unsigned ct = a.x + a.y + a.z + a.w;
        unsigned s = ct;
#pragma unroll
        for (int o = 1; o < 32; o <<= 1) {
            unsigned v = __shfl_down_sync(0xffffffffu, s, o);
            if (lane + o < 32) s += v;
        }
        if (lane == 0) sh->wsum[warp] = s;
        __syncthreads();
        unsigned addh = 0; tot = 0;
#pragma unroll
        for (int w = 0; w < NW; ++w) {
            unsigned v = sh->wsum[w];
            tot += v;
            if (w > warp) addh += v;
        }
        if (tot >= K_KEEP) {
            unsigned beyond = (s - ct) + addh;
            if (beyond < kth && beyond + ct >= kth) {
                unsigned carr[4] = {a.x, a.y, a.z, a.w};
                unsigned rb = beyond;
#pragma unroll
                for (int j = 3; j >= 0; --j) {
                    unsigned c = carr[j];
                    if (rb < kth && rb + c >= kth) { sh->selb = (unsigned)(tid*4+j); sh->selk = kth - rb; }
                    rb += c;
                }
            }
        }
        __syncthreads();
    }

    bool fb = (tot < K_KEEP) || (sh->selb == 1023u);
    unsigned binKey = 0, kk = 0, m = 0;
    if (!fb) {
        binKey = BOFF + sh->selb;
        kk     = sh->selk;
        // ---- compact winning-bin values (bounded append; m ~ 1-4) ----
#pragma unroll
        for (int i = 0; i < PT; ++i) {
            unsigned u = __float_as_uint(f0[i]);
            if ((u >> 14) == binKey) {
                unsigned idx = atomicAdd(&sh->cnt, 1u);
                if (idx < CMAX) sh->cbuf[idx] = u;
            }
        }
        __syncthreads();
        m = sh->cnt;
        fb = (m > CMAX);
    }

    float4* outr = reinterpret_cast<float4*>(outrow) + tid * 4;

    if (fb) {
        // ==== exact fallback: 32-step binary search in key space ====
        unsigned k0[PT];
#pragma unroll
        for (int i = 0; i < PT; ++i) k0[i] = f2k(f0[i]);
        unsigned lo = 0u, hi = 0xFFFFFFFFu;
#pragma unroll 1
        while (lo < hi) {
            unsigned mid = lo + ((hi - lo) >> 1) + ((hi - lo) & 1u);
            unsigned c = 0;
#pragma unroll
            for (int i = 0; i < PT; ++i) c += (k0[i] >= mid) ? 1u : 0u;
            c = __reduce_add_sync(0xffffffffu, c);
            if (lane == 0) sh->wsum[warp] = c;
            __syncthreads();
            if (warp == 0) {
                unsigned v = (lane < NW) ? sh->wsum[lane] : 0u;
#pragma unroll
                for (int o = 4; o > 0; o >>= 1) v += __shfl_down_sync(0xffffffffu, v, o);
                if (lane == 0) sh->stot = v;
            }
            __syncthreads();
            if (sh->stot >= K_KEEP) lo = mid; else hi = mid - 1u;
        }
        const unsigned T = lo;
        unsigned cg = 0, ceq = 0;
#pragma unroll
        for (int i = 0; i < PT; ++i) {
            cg  += (k0[i] > T)  ? 1u : 0u;
            ceq += (k0[i] == T) ? 1u : 0u;
        }
        {
            unsigned c = __reduce_add_sync(0xffffffffu, cg);
            if (lane == 0) sh->wsum[warp] = c;
            __syncthreads();
            if (warp == 0) {
                unsigned v = (lane < NW) ? sh->wsum[lane] : 0u;
#pragma unroll
                for (int o = 4; o > 0; o >>= 1) v += __shfl_down_sync(0xffffffffu, v, o);
                if (lane == 0) sh->stot = v;
            }
            __syncthreads();
        }
        const unsigned need = K_KEEP - sh->stot;
        __syncthreads();
        unsigned p = ceq;
#pragma unroll
        for (int o = 1; o < 32; o <<= 1) {
            unsigned v = __shfl_up_sync(0xffffffffu, p, o);
            if (lane >= o) p += v;
        }
        if (lane == 31) sh->wsum[warp] = p;
        __syncthreads();
        unsigned woff = 0;
#pragma unroll
        for (int w = 0; w < NW; ++w) if (w < warp) woff += sh->wsum[w];
        unsigned rank = woff + p - ceq;
#pragma unroll
        for (int j = 0; j < 4; ++j) {
            float r[4];
#pragma unroll
            for (int c2 = 0; c2 < 4; ++c2) {
                unsigned k = k0[j * 4 + c2];
                bool eq = (k == T);
                bool keep = (k > T) || (eq && (rank < need));
                r[c2] = keep ? k2f(k) : 0.0f;
                rank += eq ? 1u : 0u;
            }
            outr[j] = make_float4(r[0], r[1], r[2], r[3]);
        }
        return;
    }

    // ---- warp-0 exact select within bin ----
    if (warp == 0) {
        if (m <= 32u) {
            unsigned orig = (lane < (int)m) ? sh->cbuf[lane] : 0u;
            unsigned v = orig;
#pragma unroll
            for (int k = 2; k <= 32; k <<= 1) {
#pragma unroll
                for (int j = k >> 1; j > 0; j >>= 1) {
                    unsigned o = __shfl_xor_sync(0xffffffffu, v, j);
                    bool dirUp   = ((lane & k) == 0);
                    bool takeMax = ((lane & j) != 0);
                    unsigned mn = umin(v, o), mx = umax(v, o);
                    v = (dirUp == takeMax) ? mx : mn;
                }
            }
            unsigned T = __shfl_sync(0xffffffffu, v, 32 - (int)kk);
            unsigned cg = __reduce_add_sync(0xffffffffu, (orig > T)  ? 1u : 0u);
            unsigned ce = __reduce_add_sync(0xffffffffu, (orig == T) ? 1u : 0u);
            if (lane == 0) { sh->sT = T; sh->sneed = kk - cg; sh->sneq = ce; }
        } else {
            unsigned lo = binKey << 14, hi = (binKey << 14) | 0x3FFFu;
#pragma unroll 1
            while (lo < hi) {
                unsigned mid = lo + ((hi - lo) >> 1) + ((hi - lo) & 1u);
                unsigned c = 0;
                for (unsigned j = lane; j < m; j += 32u) c += (sh->cbuf[j] >= mid) ? 1u : 0u;
                c = __reduce_add_sync(0xffffffffu, c);
                if (c >= kk) lo = mid; else hi = mid - 1u;
            }
            unsigned cg = 0, ce = 0;
            for (unsigned j = lane; j < m; j += 32u) {
                unsigned v = sh->cbuf[j];
                cg += (v > lo)  ? 1u : 0u;
                ce += (v == lo) ? 1u : 0u;
            }
            cg = __reduce_add_sync(0xffffffffu, cg);
            ce = __reduce_add_sync(0xffffffffu, ce);
            if (lane == 0) { sh->sT = lo; sh->sneed = kk - cg; sh->sneq = ce; }
        }
    }
    __syncthreads();

    const unsigned need = sh->sneed;
    const unsigned neq  = sh->sneq;
    const float    Tf   = __uint_as_float(sh->sT);   // positive float

    if (need == neq) {
        // ---- fast emit: keep everything >= Tf ----
#pragma unroll
        for (int j = 0; j < 4; ++j) {
            float4 o;
            o.x = (f0[j*4+0] >= Tf) ? f0[j*4+0] : 0.0f;
            o.y = (f0[j*4+1] >= Tf) ? f0[j*4+1] : 0.0f;
            o.z = (f0[j*4+2] >= Tf) ? f0[j*4+2] : 0.0f;
            o.w = (f0[j*4+3] >= Tf) ? f0[j*4+3] : 0.0f;
            outr[j] = o;
        }
        return;
    }

    // ---- rare tie path: stable rank, lowest index first ----
    __syncthreads();   // wsum reuse safety
    unsigned ceq = 0;
#pragma unroll
    for (int i = 0; i < PT; ++i) ceq += (f0[i] == Tf) ? 1u : 0u;
    unsigned p = ceq;
#pragma unroll
    for (int o = 1; o < 32; o <<= 1) {
        unsigned v = __shfl_up_sync(0xffffffffu, p, o);
        if (lane >= o) p += v;
    }
    if (lane == 31) sh->wsum[warp] = p;
    __syncthreads();
    unsigned woff = 0;
#pragma unroll
    for (int w = 0; w < NW; ++w) if (w < warp) woff += sh->wsum[w];
    unsigned rank = woff + p - ceq;

#pragma unroll
    for (int j = 0; j < 4; ++j) {
        float r[4];
#pragma unroll
        for (int c = 0; c < 4; ++c) {
            float f = f0[j * 4 + c];
            bool eq = (f == Tf);
            bool keep = (f > Tf) || (eq && (rank < need));
            r[c] = keep ? f : 0.0f;
            rank += eq ? 1u : 0u;
        }
        outr[j] = make_float4(r[0], r[1], r[2], r[3]);
    }
}

__global__ __launch_bounds__(NT, 6)
void topk_keep_kernel(const float* __restrict__ x, float* __restrict__ out, int rows)
{
    __shared__ __align__(16) float fbuf[D_DIM];   // 16KB: row B staging
    __shared__ Sh sh;

    const int tid  = threadIdx.x;
    const int lane = tid & 31;
    const int warp = tid >> 5;
    const int rowA = 2 * blockIdx.x;
    const int rowB = rowA + 1;
    const unsigned sbase = (unsigned)__cvta_generic_to_shared(fbuf);

    // ---- issue LDG for row A (registers) ----
    const float4* xrA = reinterpret_cast<const float4*>(x + (size_t)rowA * D_DIM) + tid * 4;
    float fA[PT];
    {
        float4 v0 = xrA[0], v1 = xrA[1], v2 = xrA[2], v3 = xrA[3];
        fA[0]=v0.x;  fA[1]=v0.y;  fA[2]=v0.z;  fA[3]=v0.w;
        fA[4]=v1.x;  fA[5]=v1.y;  fA[6]=v1.z;  fA[7]=v1.w;
        fA[8]=v2.x;  fA[9]=v2.y;  fA[10]=v2.z; fA[11]=v2.w;
        fA[12]=v3.x; fA[13]=v3.y; fA[14]=v3.z; fA[15]=v3.w;
    }

    // ---- issue cp.async for row B (smem), overlaps ALL of row A's work ----
    if (rowB < rows) {
        const char* g = (const char*)(x + (size_t)rowB * D_DIM);
#pragma unroll
        for (int r = 0; r < 4; ++r) {
            unsigned off = (unsigned)(r * 4096 + tid * 16);
            asm volatile("cp.async.cg.shared.global [%0], [%1], 16;"
                         :: "r"(sbase + off), "l"(g + off));
        }
        asm volatile("cp.async.commit_group;" ::: "memory");
    }

    zero_state(&sh, tid);
    __syncthreads();

    // ================= row A =================
    process_row(fA, out + (size_t)rowA * D_DIM, &sh, tid, lane, warp);
    __syncthreads();          // row A's smem use complete

    if (rowB >= rows) return;

    // ================= row B =================
    zero_state(&sh, tid);
    asm volatile("cp.async.wait_group 0;" ::: "memory");
    __syncthreads();          // fbuf visible + state zeroed

    float fB[PT];
    {
        const float4* sb = reinterpret_cast<const float4*>(fbuf) + tid * 4;
        float4 v0 = sb[0], v1 = sb[1], v2 = sb[2], v3 = sb[3];
        fB[0]=v0.x;  fB[1]=v0.y;  fB[2]=v0.z;  fB[3]=v0.w;
        fB[4]=v1.x;  fB[5]=v1.y;  fB[6]=v1.z;  fB[7]=v1.w;
        fB[8]=v2.x;  fB[9]=v2.y;  fB[10]=v2.z; fB[11]=v2.w;
        fB[12]=v3.x; fB[13]=v3.y; fB[14]=v3.z; fB[15]=v3.w;
    }
    process_row(fB, out + (size_t)rowB * D_DIM, &sh, tid, lane, warp);
}

extern "C" void kernel_launch(void* const* d_in, const int* in_sizes, int n_in,
                              void* d_out, int out_size) {
    const float* x = (const float*)d_in[0];
    float* out = (float*)d_out;
    int rows = out_size / D_DIM;       // 16384
    int grid = (rows + 1) / 2;         // 8192 CTAs, 2 rows each
    topk_keep_kernel<<<grid, NT>>>(x, out, rows);
}